// round 6
// baseline (speedup 1.0000x reference)
#include <cuda_runtime.h>
#include <cstdint>
#include <math.h>

// Problem constants
#define BB 64
#define SS 1024
#define II 512
#define HH 512
#define NPANEL 128   // persistent CTAs: 64 panels per layer, 1 CTA/SM
#define JPC 8        // hidden units per CTA
#define TPB 128
#define KT 64        // k-chunk staged in SMEM
#define NCHUNK 16    // 1024 / 64
#define AP 66        // A smem row pitch (even -> 8B LDS, 2-way STS conflicts only)

#define WS_FLOATS (1024*32)          // duplicated weight panel: [k][32]
#define AS_FLOATS (KT*AP)
#define SMEM_BYTES ((WS_FLOATS + 2*AS_FLOATS)*4)   // 164864 B (fits 228KB carveout, 1 CTA/SM)

typedef unsigned long long ull;

// Scratch (device globals: allocation-free per harness rules)
__device__ float g_Wpanel[NPANEL*1024*16];  // [panel][k][16] cols interleaved (gate j, cand j)
__device__ float g_h0[2][BB*HH];            // ping-pong hidden, layer 0
__device__ float g_h1[2][BB*HH];            // ping-pong hidden, layer 1
__device__ unsigned g_arrive;               // grid-barrier monotonic arrival counter

__device__ __forceinline__ ull ffma2(ull a, ull b, ull c){
    ull d;
    asm("fma.rn.f32x2 %0, %1, %2, %3;" : "=l"(d) : "l"(a), "l"(b), "l"(c));
    return d;
}
__device__ __forceinline__ void unpack2(ull v, float& lo, float& hi){
    asm("mov.b64 {%0, %1}, %2;" : "=f"(lo), "=f"(hi) : "l"(v));
}

// Build combined, column-interleaved weight panels:
// panel p: layer l = p>>6, hidden units j0..j0+7 with j0 = (p&63)*8.
// g_Wpanel[p][k][2*jj+0] = gate weight Wg[l][k][j]   (Wg rows already [inp;h] ordered)
// g_Wpanel[p][k][2*jj+1] = cand weight (k<512 ? Wi[l][k][j] : Wh[l][k-512][j])
__global__ void prep_kernel(const float* __restrict__ Wg,
                            const float* __restrict__ Wi,
                            const float* __restrict__ Wh){
    int idx = blockIdx.x * blockDim.x + threadIdx.x;
    if (idx >= NPANEL*1024*16) return;
    int cc = idx & 15;
    int k  = (idx >> 4) & 1023;
    int p  = idx >> 14;
    int l  = p >> 6;
    int j  = (p & 63)*JPC + (cc >> 1);
    float v;
    if ((cc & 1) == 0) {
        v = Wg[(size_t)(l*1024 + k)*512 + j];
    } else {
        v = (k < II) ? Wi[(size_t)(l*512 + k)*512 + j]
                     : Wh[(size_t)(l*512 + (k - II))*512 + j];
    }
    g_Wpanel[idx] = v;
}

// Zero hidden state + barrier counter (runs at the start of every replay).
__global__ void init_kernel(){
    int i = blockIdx.x * blockDim.x + threadIdx.x;
    if (i == 0) g_arrive = 0u;
    if (i < BB*HH){
        g_h0[0][i] = 0.f; g_h0[1][i] = 0.f;
        g_h1[0][i] = 0.f; g_h1[1][i] = 0.f;
    }
}

// Persistent kernel: 128 CTAs (one per SM, all co-resident at occ=1), looping
// over phases s=0..SS with a device grid barrier between phases.
//   phase s:  CTAs l==0 compute h0[s]   = gru(x[:,s,:], h0[s-1])   (s < SS)
//             CTAs l==1 compute h1[s-1] = gru(h0[s-1],  h1[s-2])   (s >= 1)
// Single barrier per phase is sufficient: a CTA only arrives after finishing
// ALL its phase-s reads and writes, so phase s+1's WAR on the ping-pong
// buffers is safe.
__global__ void __launch_bounds__(TPB, 1)
persist_kernel(const float* __restrict__ x, const float* __restrict__ bg,
               const float* __restrict__ bi, float* __restrict__ out,
               int out_size)
{
    const int p = blockIdx.x;
    const int l = p >> 6;
    const int t = threadIdx.x;

    extern __shared__ float smf[];
    float* ws  = smf;                    // [1024][32] duplicated weights (persistent)
    float* as0 = smf + WS_FLOATS;        // [KT][AP] A tile, buffer 0
    float* as1 = as0 + AS_FLOATS;        // buffer 1

    // ---- load weight panel into SMEM ONCE, duplicating scalars into pairs for FFMA2 ----
    {
        const float4* gw = ((const float4*)g_Wpanel) + (size_t)p * 4096;
        float4* ws4 = (float4*)ws;
        #pragma unroll
        for (int it = 0; it < 32; ++it){
            int i = t + it*TPB;                 // 0..4095 float4s
            float4 v = gw[i];
            int k = i >> 2, q = i & 3;
            ws4[k*8 + q*2 + 0] = make_float4(v.x, v.x, v.y, v.y);
            ws4[k*8 + q*2 + 1] = make_float4(v.z, v.z, v.w, v.w);
        }
    }
    __syncthreads();

    const int jj = t >> 4;          // 0..7 hidden unit within panel
    const int m0 = (t & 15) * 4;    // 4 batch rows
    const int klocal = t & 63;
    const int mb     = t >> 6;      // 0 or 1
    const int j = (p & 63)*JPC + jj;
    const float bgv = bg[l*HH + j];
    const float biv = bi[l*HH + j];
    const float* wbase = ws + jj*4;

    unsigned bar_target = 0;

    #pragma unroll 1
    for (int s = 0; s <= SS; ++s){
        const bool active = !((l == 0 && s == SS) || (l == 1 && s == 0));
        if (active){
            int pb = s & 1;
            const float* h0prev  = g_h0[pb ^ 1];
            float*       h0out   = g_h0[pb];
            const float* h1prev2 = g_h1[pb];
            float*       h1out   = g_h1[pb ^ 1];

            const float* baseLo; size_t strideLo;
            const float* baseHi;
            const float* hupd; float* hout;
            if (l == 0){
                baseLo = x + (size_t)s * II;  strideLo = (size_t)SS * II;
                baseHi = h0prev;  hupd = h0prev;  hout = h0out;
            } else {
                baseLo = h0prev;  strideLo = HH;
                baseHi = h1prev2; hupd = h1prev2; hout = h1out;
            }

            // ---- A staging: transposed [k][m] tiles, double-buffered ----
            float pf[32];
            auto prefetch = [&](int c){
                int k = c*KT + klocal;
                #pragma unroll
                for (int i = 0; i < 32; ++i){
                    int m = 2*i + mb;
                    pf[i] = (k < II) ? baseLo[(size_t)m*strideLo + k]
                                     : baseHi[(size_t)m*HH + (k - II)];
                }
            };
            auto sts = [&](float* buf){
                #pragma unroll
                for (int i = 0; i < 32; ++i)
                    buf[klocal*AP + 2*i + mb] = pf[i];
            };

            ull ag0 = 0, ag1 = 0, ac0 = 0, ac1 = 0;
            auto compute = [&](const float* buf, int c){
                const float* wc = wbase + c*KT*32;
                #pragma unroll
                for (int kk = 0; kk < KT; ++kk){
                    const float* ar = buf + kk*AP + m0;
                    ull a01 = *(const ull*)(ar);
                    ull a23 = *(const ull*)(ar + 2);
                    // weights: gate-pair + cand-pair are 16B contiguous, 16B aligned
                    ulonglong2 w2 = *(const ulonglong2*)(wc + kk*32);
                    ag0 = ffma2(a01, w2.x, ag0);
                    ag1 = ffma2(a23, w2.x, ag1);
                    ac0 = ffma2(a01, w2.y, ac0);
                    ac1 = ffma2(a23, w2.y, ac1);
                }
            };

            prefetch(0);
            sts(as0);
            __syncthreads();
            prefetch(1);
            #pragma unroll 1
            for (int c = 0; c < NCHUNK; ++c){
                float* cur = (c & 1) ? as1 : as0;
                float* nxt = (c & 1) ? as0 : as1;
                compute(cur, c);
                if (c + 1 < NCHUNK) sts(nxt);
                __syncthreads();
                if (c + 2 < NCHUNK) prefetch(c + 2);
            }

            // ---- epilogue: GRU update ----
            float gv[4], cv[4];
            unpack2(ag0, gv[0], gv[1]); unpack2(ag1, gv[2], gv[3]);
            unpack2(ac0, cv[0], cv[1]); unpack2(ac1, cv[2], cv[3]);
            #pragma unroll
            for (int r = 0; r < 4; ++r){
                int m = m0 + r;
                float zin = gv[r] + bgv;
                float z   = __fdividef(1.f, 1.f + __expf(-zin));
                float cin = cv[r] + biv;
                float av  = fabsf(cin);
                float e   = __expf(-2.f*av);
                float cd  = copysignf(__fdividef(1.f - e, 1.f + e), cin);
                float hp  = hupd[(size_t)m*HH + j];
                float hn  = hp + z*(cd - hp);
                hout[(size_t)m*HH + j] = hn;
                if (l == 1)
                    out[(size_t)m*SS*HH + (size_t)(s-1)*HH + j] = hn;
            }
        }

        // ---- grid barrier (monotonic counter; reset by init_kernel each replay) ----
        bar_target += NPANEL;
        __syncthreads();
        if (t == 0){
            __threadfence();
            atomicAdd(&g_arrive, 1u);
            unsigned v;
            do {
                asm volatile("ld.acquire.gpu.global.u32 %0, [%1];"
                             : "=r"(v) : "l"(&g_arrive) : "memory");
            } while (v < bar_target);
        }
        __syncthreads();
    }

    // ---- tail: final hidden states appended after output ----
    // h0[S-1] ended in g_h0[1] (written phase S-1, pb=1);
    // h1[S-1] ended in g_h1[1] (written phase S,   pb^1=1).
    long long base = (long long)BB*SS*HH;
    if (base + 2LL*BB*HH <= (long long)out_size){
        for (int i = p*TPB + t; i < BB*HH; i += NPANEL*TPB){
            out[base + i]         = g_h0[1][i];
            out[base + BB*HH + i] = g_h1[1][i];
        }
    }
}

extern "C" void kernel_launch(void* const* d_in, const int* in_sizes, int n_in,
                              void* d_out, int out_size)
{
    const float* x  = (const float*)d_in[0];
    const float* Wg = (const float*)d_in[1];
    const float* bg = (const float*)d_in[2];
    const float* Wi = (const float*)d_in[3];
    const float* bi = (const float*)d_in[4];
    const float* Wh = (const float*)d_in[5];
    float* out = (float*)d_out;

    cudaFuncSetAttribute(persist_kernel, cudaFuncAttributeMaxDynamicSharedMemorySize, SMEM_BYTES);

    prep_kernel<<<(NPANEL*1024*16 + 255)/256, 256>>>(Wg, Wi, Wh);
    init_kernel<<<(BB*HH + 255)/256, 256>>>();
    persist_kernel<<<NPANEL, TPB, SMEM_BYTES>>>(x, bg, bi, out, out_size);
}